// round 3
// baseline (speedup 1.0000x reference)
#include <cuda_runtime.h>

#define NN   6144          // nodes
#define INF_ 256           // in features
#define H    4             // heads
#define D    64            // hidden per head
#define HD   256           // H*D
#define LOG2E 1.4426950408889634f

#define JSPLIT 8
#define BI 64
#define BJ 32
#define NJ (NN / JSPLIT)       // 768 columns per split
#define NCH (NJ / BJ)          // 24 chunks

// ---------------- scratch (device globals; no allocation allowed) ----------
__device__ float g_ht [NN * HD];                  // 6.29 MB : ht[n][h*64+d]
__device__ float g_src[H * NN];                   // pre-scaled by log2e
__device__ float g_tgt[H * NN];
__device__ float g_O  [(size_t)JSPLIT * H * NN * D];   // 50.3 MB partial numerators
__device__ float g_den[JSPLIT * H * NN];               // partial denominators

// ---------------- kernel 1: ht = h @ W  (6144x256 @ 256x256) ---------------
__global__ void __launch_bounds__(256) gemm_htW(const float* __restrict__ A,
                                                const float* __restrict__ B) {
    __shared__ float sA[16 * 68];   // [k][m] transposed, padded
    __shared__ float sB[16 * 64];   // [k][n]
    int t  = threadIdx.x;
    int n0 = blockIdx.x * 64;
    int m0 = blockIdx.y * 64;
    int tx = t & 15, ty = t >> 4;

    float acc[4][4] = {};
    int mA = t >> 2, kA = (t & 3) * 4;   // A loader coords
    int kB = t >> 4, nB = (t & 15) * 4;  // B loader coords

    for (int k0 = 0; k0 < INF_; k0 += 16) {
        float4 av = *(const float4*)&A[(m0 + mA) * INF_ + k0 + kA];
        float4 bv = *(const float4*)&B[(k0 + kB) * HD + n0 + nB];
        sA[(kA + 0) * 68 + mA] = av.x;
        sA[(kA + 1) * 68 + mA] = av.y;
        sA[(kA + 2) * 68 + mA] = av.z;
        sA[(kA + 3) * 68 + mA] = av.w;
        *(float4*)&sB[kB * 64 + nB] = bv;
        __syncthreads();
#pragma unroll
        for (int k = 0; k < 16; k++) {
            float4 a4 = *(float4*)&sA[k * 68 + ty * 4];
            float4 b4 = *(float4*)&sB[k * 64 + tx * 4];
            float ar[4] = {a4.x, a4.y, a4.z, a4.w};
            float br[4] = {b4.x, b4.y, b4.z, b4.w};
#pragma unroll
            for (int i = 0; i < 4; i++)
#pragma unroll
                for (int j = 0; j < 4; j++)
                    acc[i][j] += ar[i] * br[j];
        }
        __syncthreads();
    }
#pragma unroll
    for (int i = 0; i < 4; i++) {
        float4 o = make_float4(acc[i][0], acc[i][1], acc[i][2], acc[i][3]);
        *(float4*)&g_ht[(size_t)(m0 + ty * 4 + i) * HD + n0 + tx * 4] = o;
    }
}

// ---------------- kernel 2: src/tgt projections ----------------------------
// one warp per (node, head); lanes span d in float2. Pre-scale by log2e.
__global__ void __launch_bounds__(256) src_tgt_k(const float* __restrict__ a) {
    int gw   = (blockIdx.x * blockDim.x + threadIdx.x) >> 5;
    int lane = threadIdx.x & 31;
    if (gw >= NN * H) return;
    int n = gw >> 2, h = gw & 3;
    float2 v  = *(const float2*)&g_ht[(size_t)n * HD + h * D + 2 * lane];
    const float* ap = a + h * 2 * D;                  // a[h][0:128]
    float2 as = *(const float2*)&ap[2 * lane];        // a_src
    float2 at = *(const float2*)&ap[D + 2 * lane];    // a_tgt
    float s = v.x * as.x + v.y * as.y;
    float tt = v.x * at.x + v.y * at.y;
#pragma unroll
    for (int off = 16; off > 0; off >>= 1) {
        s  += __shfl_xor_sync(0xffffffffu, s, off);
        tt += __shfl_xor_sync(0xffffffffu, tt, off);
    }
    if (lane == 0) {
        g_src[h * NN + n] = s  * LOG2E;
        g_tgt[h * NN + n] = tt * LOG2E;
    }
}

// ---------------- kernel 3: fused masked-exp + P@V (per head, per j-split) -
// block = 64 threads (2 warps), tile: 64 rows x 64 d, chunks of 32 columns.
// No max subtraction needed (scores are O(±6) pre-exp2); split partials add.
__global__ void __launch_bounds__(64) gat_attn(const int* __restrict__ adj) {
    __shared__ float sW[BJ * 68];   // [k][r], stride 68 (16B aligned, low-conflict)
    __shared__ float sV[BJ * D];    // [k][d]
    __shared__ float sSrc[BI];

    int t  = threadIdx.x;
    int i0 = blockIdx.x * BI;
    int h  = blockIdx.y;
    int js = blockIdx.z;
    int j0base = js * NJ;

    if (t < BI) sSrc[t] = g_src[h * NN + i0 + t];
    __syncthreads();

    float acc[8][8] = {};
    float dacc[8]   = {};
    int jlane = t & 31, rb = t >> 5;       // w-gen mapping
    int tr = t & 7, tc = t >> 3;           // gemm mapping: rows tr*8.., d tc*8..

    for (int c = 0; c < NCH; c++) {
        int j0 = j0base + c * BJ;
        // stage V tile (32 x 64 f32) from g_ht
#pragma unroll
        for (int i = 0; i < 8; i++) {
            int q = t + 64 * i;
            int k = q >> 4, d4 = (q & 15) * 4;
            *(float4*)&sV[k * D + d4] =
                *(const float4*)&g_ht[(size_t)(j0 + k) * HD + h * D + d4];
        }
        // generate weights: w = adj ? 2^leaky(src'+tgt') : 0
        // Two 16-row batches: batch the adj LDGs first for deep MLP, then
        // the MUFU/ALU tail consumes them (LDG lat ~380-577 cyc hidden).
        float tg = g_tgt[h * NN + j0 + jlane];
        const int* ap = adj + (size_t)(i0 + rb * 32) * NN + j0 + jlane;
#pragma unroll
        for (int half = 0; half < 2; half++) {
            int avb[16];
#pragma unroll
            for (int m = 0; m < 16; m++)
                avb[m] = __ldg(&ap[(size_t)(half * 16 + m) * NN]);
#pragma unroll
            for (int m = 0; m < 16; m++) {
                int r  = rb * 32 + half * 16 + m;
                float e  = sSrc[r] + tg;
                float lk = fmaxf(e, 0.2f * e);
                float w;
                asm("ex2.approx.ftz.f32 %0, %1;" : "=f"(w) : "f"(lk));
                w = avb[m] ? w : 0.0f;
                sW[jlane * 68 + r] = w;
            }
        }
        __syncthreads();
        // O += P @ V  (8x8 register tile per thread), denom via tc==0 column
#pragma unroll
        for (int k = 0; k < BJ; k++) {
            float4 p0 = *(float4*)&sW[k * 68 + tr * 8];
            float4 p1 = *(float4*)&sW[k * 68 + tr * 8 + 4];
            float4 v0 = *(float4*)&sV[k * D + tc * 8];
            float4 v1 = *(float4*)&sV[k * D + tc * 8 + 4];
            float p[8] = {p0.x, p0.y, p0.z, p0.w, p1.x, p1.y, p1.z, p1.w};
            float v[8] = {v0.x, v0.y, v0.z, v0.w, v1.x, v1.y, v1.z, v1.w};
#pragma unroll
            for (int i = 0; i < 8; i++)
#pragma unroll
                for (int j = 0; j < 8; j++)
                    acc[i][j] += p[i] * v[j];
            if (tc == 0) {
#pragma unroll
                for (int i = 0; i < 8; i++) dacc[i] += p[i];
            }
        }
        __syncthreads();
    }

    float* Op = &g_O[((size_t)(js * H + h) * NN) * D];
#pragma unroll
    for (int i = 0; i < 8; i++) {
        int r = i0 + tr * 8 + i;
        *(float4*)&Op[(size_t)r * D + tc * 8] =
            make_float4(acc[i][0], acc[i][1], acc[i][2], acc[i][3]);
        *(float4*)&Op[(size_t)r * D + tc * 8 + 4] =
            make_float4(acc[i][4], acc[i][5], acc[i][6], acc[i][7]);
    }
    if (tc == 0) {
#pragma unroll
        for (int i = 0; i < 8; i++)
            g_den[(js * H + h) * NN + i0 + tr * 8 + i] = dacc[i];
    }
}

// ---------------- kernel 4: merge splits, normalize, mean over heads -------
__global__ void __launch_bounds__(256) reduce_out(float* __restrict__ out) {
    int idx = blockIdx.x * blockDim.x + threadIdx.x;
    if (idx >= NN * D) return;
    int i = idx >> 6, d = idx & 63;
    float s = 0.0f;
#pragma unroll
    for (int h = 0; h < H; h++) {
        float o = 0.0f, den = 0.0f;
#pragma unroll
        for (int js = 0; js < JSPLIT; js++) {
            o   += g_O[((size_t)(js * H + h) * NN + i) * D + d];
            den += g_den[(js * H + h) * NN + i];
        }
        if (den == 0.0f) den = 1.0f;   // unreachable with this graph density
        s += __fdividef(o, den);
    }
    out[idx] = 0.25f * s;
}

// ---------------- launch ---------------------------------------------------
extern "C" void kernel_launch(void* const* d_in, const int* in_sizes, int n_in,
                              void* d_out, int out_size) {
    const float* h   = (const float*)d_in[0];
    const int*   adj = (const int*)  d_in[1];
    const float* W   = (const float*)d_in[2];
    const float* a   = (const float*)d_in[3];
    float* out = (float*)d_out;

    gemm_htW<<<dim3(HD / 64, NN / 64), 256>>>(h, W);
    src_tgt_k<<<(NN * H * 32 + 255) / 256, 256>>>(a);
    gat_attn<<<dim3(NN / BI, H, JSPLIT), 64>>>(adj);
    reduce_out<<<(NN * D + 255) / 256, 256>>>(out);
}